// round 1
// baseline (speedup 1.0000x reference)
#include <cuda_runtime.h>
#include <cuda_bf16.h>

// Fused: y = AdaptiveAvgPool2d(56)( ReLU(x * std + mean) )
// for three groups of patches (s=24, 32, 48), 32 patches each, C=256.
// Output: [96, 256, 56, 56] float32.
//
// Since s < 56 for all groups, every adaptive-pool bin covers 1 or 2 source
// rows/cols => each output pixel averages at most 2x2 inputs. One CTA per
// (patch, channel) plane; plane staged in smem with affine+ReLU applied on
// load; output written as coalesced float4.

#define C_CH 256
#define OUTW 56

__global__ __launch_bounds__(256, 8)
void ppin_fused_kernel(const float* __restrict__ p24,
                       const float* __restrict__ p32,
                       const float* __restrict__ p48,
                       const float* __restrict__ smean,
                       const float* __restrict__ sstd,
                       float* __restrict__ out)
{
    __shared__ float sm[48 * 48];

    const int bid = blockIdx.x;          // plane index = n*256 + c
    const int n   = bid >> 8;
    const int c   = bid & 255;

    int s;
    const float* src;
    if (n < 32) {
        s = 24;
        src = p24 + ((size_t)n * C_CH + c) * (24 * 24);
    } else if (n < 64) {
        s = 32;
        src = p32 + ((size_t)(n - 32) * C_CH + c) * (32 * 32);
    } else {
        s = 48;
        src = p48 + ((size_t)(n - 64) * C_CH + c) * (48 * 48);
    }

    const float m  = smean[bid];
    const float sd = sstd[bid];

    // Stage plane with affine + ReLU applied.
    const int tot = s * s;
    for (int i = threadIdx.x; i < tot; i += 256) {
        float v = fmaf(src[i], sd, m);
        sm[i] = v > 0.0f ? v : 0.0f;
    }
    __syncthreads();

    // Each thread writes float4 output chunks: 56*56/4 = 784 per plane.
    float4* outp = (float4*)(out + (size_t)bid * (OUTW * OUTW));

    for (int q = threadIdx.x; q < OUTW * (OUTW / 4); q += 256) {
        const int i  = q / (OUTW / 4);        // output row
        const int j0 = (q % (OUTW / 4)) * 4;  // first output col of this float4

        const int r0 = (i * s) / OUTW;
        const int r1 = ((i + 1) * s + (OUTW - 1)) / OUTW;   // ceil
        const float invr = (r1 - r0 == 1) ? 1.0f : 0.5f;

        float res[4];
        #pragma unroll
        for (int k = 0; k < 4; k++) {
            const int j  = j0 + k;
            const int c0 = (j * s) / OUTW;
            const int c1 = ((j + 1) * s + (OUTW - 1)) / OUTW;
            const float invc = (c1 - c0 == 1) ? 1.0f : 0.5f;

            float acc = 0.0f;
            #pragma unroll 2
            for (int r = r0; r < r1; r++) {
                acc += sm[r * s + c0];
                if (c1 - c0 == 2) acc += sm[r * s + c0 + 1];
            }
            res[k] = acc * (invr * invc);
        }
        outp[q] = make_float4(res[0], res[1], res[2], res[3]);
    }
}

extern "C" void kernel_launch(void* const* d_in, const int* in_sizes, int n_in,
                              void* d_out, int out_size)
{
    const float* p24   = (const float*)d_in[0];
    const float* p32   = (const float*)d_in[1];
    const float* p48   = (const float*)d_in[2];
    const float* smean = (const float*)d_in[3];
    const float* sstd  = (const float*)d_in[4];
    float* out = (float*)d_out;

    const int planes = 96 * C_CH;  // 24576
    ppin_fused_kernel<<<planes, 256>>>(p24, p32, p48, smean, sstd, out);
}

// round 2
// speedup vs baseline: 1.4356x; 1.4356x over previous
#include <cuda_runtime.h>
#include <cuda_bf16.h>

// Fused: y = AdaptiveAvgPool2d(56)( ReLU(x * std + mean) )
// Groups: s=24,32,48, 32 patches each, C=256. Output [96,256,56,56] f32.
//
// s < 56 => every adaptive bin spans 1 or 2 source rows/cols, so each output
// pixel = weighted avg of a 2x2 neighborhood (second row/col masked by m=0).
// One CTA per (patch, channel) plane. Bin tables (identical for rows & cols)
// are computed ONCE per CTA into smem; the pixel loop is branchless FFMA+LDS.

#define C_CH 256
#define OUTW 56
#define TPB  196   // 196 threads * 4 quads = 784 float4 = 56*56 pixels

__global__ __launch_bounds__(TPB, 8)
void ppin_fused_kernel(const float* __restrict__ p24,
                       const float* __restrict__ p32,
                       const float* __restrict__ p48,
                       const float* __restrict__ smean,
                       const float* __restrict__ sstd,
                       float* __restrict__ out)
{
    __shared__ float sm[48 * 48 + 49];   // plane + zeroed tail pad (row + 1)
    __shared__ int   cb[56];             // col byte offset: c0*4
    __shared__ int   rb[56];             // row byte offset: r0*s*4
    __shared__ float wt[56];             // 1/count  (1.0 or 0.5)
    __shared__ float mt[56];             // count-1  (0.0 or 1.0)

    const int bid = blockIdx.x;          // plane = n*256 + c
    const int n   = bid >> 8;
    const int c   = bid & 255;

    int s;
    const float* src;
    if (n < 32) {
        s = 24; src = p24 + ((size_t)n * C_CH + c) * (24 * 24);
    } else if (n < 64) {
        s = 32; src = p32 + ((size_t)(n - 32) * C_CH + c) * (32 * 32);
    } else {
        s = 48; src = p48 + ((size_t)(n - 64) * C_CH + c) * (48 * 48);
    }
    const int ss = s * s;

    // ── bin tables (once per CTA; rows & cols share the formula) ──
    if (threadIdx.x < OUTW) {
        const int t  = threadIdx.x;
        const int c0 = (t * s) / OUTW;
        const int c1 = ((t + 1) * s + (OUTW - 1)) / OUTW;   // ceil
        cb[t] = c0 * 4;
        rb[t] = c0 * s * 4;
        wt[t] = (c1 - c0 == 1) ? 1.0f : 0.5f;
        mt[t] = (float)(c1 - c0 - 1);
    }

    const float m  = smean[bid];
    const float sd = sstd[bid];

    // ── stage plane with affine + ReLU, vectorized LDG.128 ──
    {
        const float4* src4 = (const float4*)src;
        float4*       sm4  = (float4*)sm;
        const int nq = ss >> 2;
        for (int i = threadIdx.x; i < nq; i += TPB) {
            float4 v = src4[i];
            float4 r;
            r.x = fmaxf(fmaf(v.x, sd, m), 0.0f);
            r.y = fmaxf(fmaf(v.y, sd, m), 0.0f);
            r.z = fmaxf(fmaf(v.z, sd, m), 0.0f);
            r.w = fmaxf(fmaf(v.w, sd, m), 0.0f);
            sm4[i] = r;
        }
        // zero the tail pad (reads past the last row are multiplied by 0,
        // but must not be inf/NaN garbage)
        for (int i = ss + threadIdx.x; i < ss + s + 1; i += TPB)
            sm[i] = 0.0f;
    }
    __syncthreads();

    // ── output: each thread writes 4 float4 quads, branchless 2x2 gather ──
    const char* smb = (const char*)sm;
    float4* outp = (float4*)(out + (size_t)bid * (OUTW * OUTW));
    const int srow = s * 4;   // row stride in bytes

    #pragma unroll
    for (int l = 0; l < 4; l++) {
        const int q  = threadIdx.x + l * TPB;   // quad id, 0..783
        const int i  = q / 14;                  // output row
        const int j0 = (q - i * 14) * 4;        // first output col

        const int   rbase = rb[i];
        const float wr    = wt[i];
        const float mr    = mt[i];

        float res[4];
        #pragma unroll
        for (int k = 0; k < 4; k++) {
            const int j = j0 + k;
            const int a = rbase + cb[j];
            const float* q0 = (const float*)(smb + a);          // row r0
            const float* q1 = (const float*)(smb + a + srow);   // row r0+1
            const float mc  = mt[j];
            const float v0  = fmaf(mc, q0[1], q0[0]);
            const float v1  = fmaf(mc, q1[1], q1[0]);
            res[k] = fmaf(mr, v1, v0) * (wr * wt[j]);
        }
        outp[q] = make_float4(res[0], res[1], res[2], res[3]);
    }
}

extern "C" void kernel_launch(void* const* d_in, const int* in_sizes, int n_in,
                              void* d_out, int out_size)
{
    const float* p24   = (const float*)d_in[0];
    const float* p32   = (const float*)d_in[1];
    const float* p48   = (const float*)d_in[2];
    const float* smean = (const float*)d_in[3];
    const float* sstd  = (const float*)d_in[4];
    float* out = (float*)d_out;

    ppin_fused_kernel<<<96 * C_CH, TPB>>>(p24, p32, p48, smean, sstd, out);
}

// round 3
// speedup vs baseline: 1.9114x; 1.3314x over previous
#include <cuda_runtime.h>
#include <cuda_bf16.h>

// Fused: y = AdaptiveAvgPool2d(56)( ReLU(x * std + mean) ), separable 2-pass.
// Template on S (24/32/48). s<56 => each adaptive bin spans 1-2 src rows/cols.
//
// Phase A: 4 threads per input row; each loads S/4 cols from GMEM, applies
//   affine+ReLU, column-pools to 14 outputs with COMPILE-TIME bin indices
//   (quarter boundaries are exact: col(14q) = qS/4), writes T[S][56] to smem.
// Phase B: out[i][j] = wr*T[r0][j] + w2*T[r0+1][j], vectorized float4:
//   2 aligned LDS.128 + 1 STG.128 per output quad. T row S zeroed (w2=0 case).

#define TROW 60   // T row stride in floats (240B: 16B-aligned, conflict-free)

template<int S>
__global__ __launch_bounds__(196, 6)
void pool_kernel(const float* __restrict__ src,
                 const float* __restrict__ smean,
                 const float* __restrict__ sstd,
                 float* __restrict__ out,   // group base
                 int sm_off)                // lo*256
{
    constexpr int NC = S / 4;             // input cols per phase-A thread
    __shared__ float T[(49) * TROW];      // 49 rows: S data rows + zero row

    const int bid = blockIdx.x;           // plane in group: n*256 + c
    const int t   = threadIdx.x;

    const float mean = smean[sm_off + bid];
    const float sd   = sstd [sm_off + bid];
    const float* plane = src + (size_t)bid * (S * S);

    // ── Phase A: load + affine + ReLU + column pool (compile-time bins) ──
    if (t < 4 * S) {
        const int r = t >> 2;
        const int q = t & 3;
        const float* rp = plane + r * S + q * NC;

        float x[NC];
        if constexpr (NC % 4 == 0) {
            #pragma unroll
            for (int k = 0; k < NC / 4; k++) {
                float4 v = ((const float4*)rp)[k];
                x[4*k+0] = v.x; x[4*k+1] = v.y; x[4*k+2] = v.z; x[4*k+3] = v.w;
            }
        } else {
            #pragma unroll
            for (int k = 0; k < NC / 2; k++) {
                float2 v = ((const float2*)rp)[k];
                x[2*k] = v.x; x[2*k+1] = v.y;
            }
        }
        #pragma unroll
        for (int k = 0; k < NC; k++)
            x[k] = fmaxf(fmaf(x[k], sd, mean), 0.0f);

        float* Trow = &T[r * TROW + q * 14];
        #pragma unroll
        for (int jl = 0; jl < 14; jl += 2) {
            float2 v;
            {
                const int c0  = (jl * S) / 56;
                const int cnt = ((jl + 1) * S + 55) / 56 - c0;
                v.x = (cnt == 1) ? x[c0] : 0.5f * (x[c0] + x[c0 + 1]);
            }
            {
                const int c0  = ((jl + 1) * S) / 56;
                const int cnt = ((jl + 2) * S + 55) / 56 - c0;
                v.y = (cnt == 1) ? x[c0] : 0.5f * (x[c0] + x[c0 + 1]);
            }
            *(float2*)(Trow + jl) = v;
        }
    }
    // zero the row past the last data row (read when row-count==1, weight 0)
    if (t < TROW) T[S * TROW + t] = 0.0f;
    __syncthreads();

    // ── Phase B: row pool, float4-vectorized; 784 quads = 4 * 196 threads ──
    float* outp = out + (size_t)bid * 3136;
    #pragma unroll
    for (int l = 0; l < 4; l++) {
        const int qd = t + l * 196;
        const int i  = qd / 14;
        const int j0 = (qd - i * 14) * 4;

        const int r0  = (i * S) / 56;
        const int cnt = ((i + 1) * S + 55) / 56 - r0;
        const float wr = (cnt == 1) ? 1.0f : 0.5f;
        const float w2 = (cnt == 1) ? 0.0f : 0.5f;

        const float4 a = *(const float4*)&T[r0 * TROW + j0];
        const float4 b = *(const float4*)&T[(r0 + 1) * TROW + j0];
        float4 res;
        res.x = fmaf(w2, b.x, wr * a.x);
        res.y = fmaf(w2, b.y, wr * a.y);
        res.z = fmaf(w2, b.z, wr * a.z);
        res.w = fmaf(w2, b.w, wr * a.w);
        *(float4*)(outp + i * 56 + j0) = res;
    }
}

extern "C" void kernel_launch(void* const* d_in, const int* in_sizes, int n_in,
                              void* d_out, int out_size)
{
    const float* p24   = (const float*)d_in[0];
    const float* p32   = (const float*)d_in[1];
    const float* p48   = (const float*)d_in[2];
    const float* smean = (const float*)d_in[3];
    const float* sstd  = (const float*)d_in[4];
    float* out = (float*)d_out;

    const int planes = 32 * 256;                 // per group
    const size_t gsz = (size_t)planes * 3136;    // output floats per group

    pool_kernel<24><<<planes, 196>>>(p24, smean, sstd, out,            0);
    pool_kernel<32><<<planes, 196>>>(p32, smean, sstd, out + gsz,      32 * 256);
    pool_kernel<48><<<planes, 196>>>(p48, smean, sstd, out + 2 * gsz,  64 * 256);
}

// round 4
// speedup vs baseline: 2.2219x; 1.1624x over previous
#include <cuda_runtime.h>
#include <cuda_bf16.h>

// Fused: y = AdaptiveAvgPool2d(56)( ReLU(x * std + mean) ), separable 2-pass.
// Single launch; per-CTA uniform dispatch to templated body (S = 24/32/48).
//
// Phase A: 4 threads per input row; each loads S/4 cols from GMEM (LDG.128/64),
//   applies affine+ReLU, column-pools to 14 outputs with COMPILE-TIME bins
//   (quarter boundaries exact: col(14q) = qS/4), writes T[S][56] (stride 60).
// Phase B: out[i][j] = wr*T[r0][j] + w2*T[r0+1][j]; 2x LDS.128 + STG.128.cs
//   per quad. T row S zeroed so the w2=0 read is finite.

#define TROW 60   // T row stride in floats (240B, 16B-aligned, conflict-free)
#define TPB  196

__device__ __forceinline__ void stcs4(float* p, float4 v) {
    asm volatile("st.global.cs.v4.f32 [%0], {%1,%2,%3,%4};"
                 :: "l"(p), "f"(v.x), "f"(v.y), "f"(v.z), "f"(v.w) : "memory");
}

template<int S>
__device__ __forceinline__
void do_plane(const float* __restrict__ plane, float mean, float sd,
              float* __restrict__ outp, float* __restrict__ T, int t)
{
    constexpr int NC = S / 4;   // input cols per phase-A thread

    // ── Phase A: load + affine + ReLU + column pool (compile-time bins) ──
    if (t < 4 * S) {
        const int r = t >> 2;
        const int q = t & 3;
        const float* rp = plane + r * S + q * NC;

        float x[NC];
        if constexpr (NC % 4 == 0) {
            #pragma unroll
            for (int k = 0; k < NC / 4; k++) {
                float4 v = ((const float4*)rp)[k];
                x[4*k+0] = v.x; x[4*k+1] = v.y; x[4*k+2] = v.z; x[4*k+3] = v.w;
            }
        } else {
            #pragma unroll
            for (int k = 0; k < NC / 2; k++) {
                float2 v = ((const float2*)rp)[k];
                x[2*k] = v.x; x[2*k+1] = v.y;
            }
        }
        #pragma unroll
        for (int k = 0; k < NC; k++)
            x[k] = fmaxf(fmaf(x[k], sd, mean), 0.0f);

        float* Trow = &T[r * TROW + q * 14];
        #pragma unroll
        for (int jl = 0; jl < 14; jl += 2) {
            float2 v;
            {
                const int c0  = (jl * S) / 56;
                const int cnt = ((jl + 1) * S + 55) / 56 - c0;
                v.x = (cnt == 1) ? x[c0] : 0.5f * (x[c0] + x[c0 + 1]);
            }
            {
                const int c0  = ((jl + 1) * S) / 56;
                const int cnt = ((jl + 2) * S + 55) / 56 - c0;
                v.y = (cnt == 1) ? x[c0] : 0.5f * (x[c0] + x[c0 + 1]);
            }
            *(float2*)(Trow + jl) = v;
        }
    }
    // zero the row past the last data row (read when row-count==1, weight 0)
    if (t < TROW) T[S * TROW + t] = 0.0f;
    __syncthreads();

    // ── Phase B: row pool, float4-vectorized; 784 quads = 4 * 196 threads ──
    #pragma unroll
    for (int l = 0; l < 4; l++) {
        const int qd = t + l * TPB;
        const int i  = qd / 14;
        const int j0 = (qd - i * 14) * 4;

        const int r0  = (i * S) / 56;
        const int cnt = ((i + 1) * S + 55) / 56 - r0;
        const float wr = (cnt == 1) ? 1.0f : 0.5f;
        const float w2 = (cnt == 1) ? 0.0f : 0.5f;

        const float4 a = *(const float4*)&T[r0 * TROW + j0];
        const float4 b = *(const float4*)&T[(r0 + 1) * TROW + j0];
        float4 res;
        res.x = fmaf(w2, b.x, wr * a.x);
        res.y = fmaf(w2, b.y, wr * a.y);
        res.z = fmaf(w2, b.z, wr * a.z);
        res.w = fmaf(w2, b.w, wr * a.w);
        stcs4(outp + i * 56 + j0, res);
    }
}

__global__ __launch_bounds__(TPB, 8)
void ppin_fused_kernel(const float* __restrict__ p24,
                       const float* __restrict__ p32,
                       const float* __restrict__ p48,
                       const float* __restrict__ smean,
                       const float* __restrict__ sstd,
                       float* __restrict__ out)
{
    __shared__ float T[49 * TROW];

    const int bid = blockIdx.x;          // plane = n*256 + c
    const int n   = bid >> 8;
    const int t   = threadIdx.x;

    const float mean = smean[bid];
    const float sd   = sstd[bid];
    float* outp = out + (size_t)bid * 3136;

    if (n < 32) {
        do_plane<24>(p24 + (size_t)bid * (24 * 24), mean, sd, outp, T, t);
    } else if (n < 64) {
        do_plane<32>(p32 + (size_t)(bid - 32 * 256) * (32 * 32), mean, sd, outp, T, t);
    } else {
        do_plane<48>(p48 + (size_t)(bid - 64 * 256) * (48 * 48), mean, sd, outp, T, t);
    }
}

extern "C" void kernel_launch(void* const* d_in, const int* in_sizes, int n_in,
                              void* d_out, int out_size)
{
    const float* p24   = (const float*)d_in[0];
    const float* p32   = (const float*)d_in[1];
    const float* p48   = (const float*)d_in[2];
    const float* smean = (const float*)d_in[3];
    const float* sstd  = (const float*)d_in[4];
    float* out = (float*)d_out;

    ppin_fused_kernel<<<96 * 256, TPB>>>(p24, p32, p48, smean, sstd, out);
}